// round 2
// baseline (speedup 1.0000x reference)
#include <cuda_runtime.h>
#include <cstdint>

#define N_NODES 100000
#define DIM     128
#define E_EDGES 500000
#define GEMM_SMEM_FLOATS (256*132 + 2*16*132 + 128)
#define GEMM_SMEM_BYTES  (GEMM_SMEM_FLOATS * 4)

// ---------------- scratch (no allocations allowed) ----------------
__device__ float g_msg_s[(size_t)N_NODES * DIM];
__device__ float g_msg_d[(size_t)N_NODES * DIM];
__device__ float g_h_s[(size_t)N_NODES * DIM];
__device__ float g_h_d[(size_t)N_NODES * DIM];
__device__ float g_inv_s[N_NODES];
__device__ float g_inv_d[N_NODES];

// ---------------- helpers ----------------
__device__ __forceinline__ void red_add_v4(float* addr, float4 v) {
    asm volatile("red.global.add.v4.f32 [%0], {%1, %2, %3, %4};"
                 :: "l"(addr), "f"(v.x), "f"(v.y), "f"(v.z), "f"(v.w)
                 : "memory");
}

// ---------------- degree ----------------
__global__ void degree_kernel(const int* __restrict__ e_src,
                              const int* __restrict__ e_dst) {
    int i = blockIdx.x * blockDim.x + threadIdx.x;
    if (i < E_EDGES) {
        atomicAdd(&g_inv_s[e_src[i]], 1.0f);
        atomicAdd(&g_inv_d[e_dst[i]], 1.0f);
    }
}

__global__ void invert_kernel() {
    int i = blockIdx.x * blockDim.x + threadIdx.x;
    if (i < N_NODES) {
        g_inv_s[i] = 1.0f / fmaxf(g_inv_s[i], 1.0f);
        g_inv_d[i] = 1.0f / fmaxf(g_inv_d[i], 1.0f);
    }
}

// ---------------- fused bidirectional scatter ----------------
// one warp per edge; lane covers one float4 (32 lanes * 4 = 128 features)
__global__ void scatter_kernel(const float* __restrict__ hs,
                               const float* __restrict__ hd,
                               const int* __restrict__ e_src,
                               const int* __restrict__ e_dst,
                               float* __restrict__ msg_s,
                               float* __restrict__ msg_d) {
    int e = blockIdx.x * 8 + (threadIdx.x >> 5);
    int lane = threadIdx.x & 31;
    int src = __ldg(&e_src[e]);
    int dst = __ldg(&e_dst[e]);
    size_t so = (size_t)src * DIM + lane * 4;
    size_t dofs = (size_t)dst * DIM + lane * 4;
    float4 vs = *(const float4*)(hs + so);
    red_add_v4(msg_d + dofs, vs);
    float4 vd = *(const float4*)(hd + dofs);
    red_add_v4(msg_s + so, vd);
}

// ---------------- fused SAGE GEMM:
//   OUT = relu( X @ Wself^T + (MSG * inv_deg) @ Wneigh^T + b )
// A = [X | MSG*inv] (100k x 256), B = [Wself ; Wneigh] transposed in SMEM,
// 128x128 CTA tile, 256 threads, 8x8 microtile, full weights SMEM-resident.
// 1/deg scaling folded into the A-tile loader (kb >= 8 -> MSG half).
__global__ __launch_bounds__(256, 1)
void sage_gemm(const float* __restrict__ X, const float* __restrict__ MSG,
               const float* __restrict__ inv,
               const float* __restrict__ Wself, const float* __restrict__ Wneigh,
               const float* __restrict__ bias, float* __restrict__ OUT, int n) {
    extern __shared__ float sm[];
    float* Bs  = sm;                       // [256][132]  (Bs[k*132+j] = Wcat[j,k])
    float* As  = sm + 256 * 132;           // [2][16][132] (As[kk*132+row])
    float* bsh = As + 2 * 16 * 132;        // [128]

    const int tid = threadIdx.x;
    const int tx = tid & 15;               // n-dir
    const int ty = tid >> 4;               // m-dir
    const int m0 = blockIdx.x * 128;

    // load weights into SMEM transposed: Bs[k][j]
    for (int i = tid; i < 128 * 128; i += 256) {
        int j = i >> 7, k = i & 127;
        Bs[k * 132 + j]         = Wself[i];
        Bs[(k + 128) * 132 + j] = Wneigh[i];
    }
    if (tid < 128) bsh[tid] = bias[tid];

    // A tile loader mapping: 512 float4 per 128x16 tile; this thread covers r0,r1
    const int r0 = tid >> 2;               // 0..63
    const int r1 = r0 + 64;                // 64..127
    const int c  = (tid & 3) << 2;         // k offset within tile (0,4,8,12)
    const int gr0 = m0 + r0, gr1 = m0 + r1;
    const float s0 = (gr0 < n) ? __ldg(&inv[gr0]) : 0.f;
    const float s1 = (gr1 < n) ? __ldg(&inv[gr1]) : 0.f;

    auto load_tile = [&](int kb, float4& u0, float4& u1) {
        const bool neigh = (kb >= 8);
        const float* srcp = neigh ? MSG : X;
        int kofs = neigh ? (kb * 16 - 128) : kb * 16;
        u0 = (gr0 < n) ? *(const float4*)(srcp + (size_t)gr0 * DIM + kofs + c)
                       : make_float4(0.f, 0.f, 0.f, 0.f);
        u1 = (gr1 < n) ? *(const float4*)(srcp + (size_t)gr1 * DIM + kofs + c)
                       : make_float4(0.f, 0.f, 0.f, 0.f);
        if (neigh) {
            u0.x *= s0; u0.y *= s0; u0.z *= s0; u0.w *= s0;
            u1.x *= s1; u1.y *= s1; u1.z *= s1; u1.w *= s1;
        }
    };
    auto store_tile = [&](float* Ab, float4 u0, float4 u1) {
        Ab[(c + 0) * 132 + r0] = u0.x;
        Ab[(c + 1) * 132 + r0] = u0.y;
        Ab[(c + 2) * 132 + r0] = u0.z;
        Ab[(c + 3) * 132 + r0] = u0.w;
        Ab[(c + 0) * 132 + r1] = u1.x;
        Ab[(c + 1) * 132 + r1] = u1.y;
        Ab[(c + 2) * 132 + r1] = u1.z;
        Ab[(c + 3) * 132 + r1] = u1.w;
    };

    float acc[8][8];
#pragma unroll
    for (int mi = 0; mi < 8; mi++)
#pragma unroll
        for (int ni = 0; ni < 8; ni++) acc[mi][ni] = 0.f;

    // prologue: tile 0
    {
        float4 u0, u1;
        load_tile(0, u0, u1);
        store_tile(As, u0, u1);
    }
    __syncthreads();

    int buf = 0;
    for (int kb = 0; kb < 16; kb++) {
        float4 n0, n1;
        bool has_next = (kb + 1) < 16;
        if (has_next) load_tile(kb + 1, n0, n1);

        const float* Asb = As + buf * 16 * 132;
        const int kbase = kb * 16;
#pragma unroll
        for (int kk = 0; kk < 16; kk++) {
            const float* ap = Asb + kk * 132 + (ty << 3);
            float4 a0 = *(const float4*)ap;
            float4 a1 = *(const float4*)(ap + 4);
            const float* bp = Bs + (kbase + kk) * 132 + (tx << 3);
            float4 b0 = *(const float4*)bp;
            float4 b1 = *(const float4*)(bp + 4);
            float a[8] = {a0.x, a0.y, a0.z, a0.w, a1.x, a1.y, a1.z, a1.w};
            float b[8] = {b0.x, b0.y, b0.z, b0.w, b1.x, b1.y, b1.z, b1.w};
#pragma unroll
            for (int mi = 0; mi < 8; mi++)
#pragma unroll
                for (int ni = 0; ni < 8; ni++)
                    acc[mi][ni] += a[mi] * b[ni];
        }
        __syncthreads();
        if (has_next) store_tile(As + (buf ^ 1) * 16 * 132, n0, n1);
        __syncthreads();
        buf ^= 1;
    }

    // epilogue: bias + relu, float4 stores
#pragma unroll
    for (int mi = 0; mi < 8; mi++) {
        int gr = m0 + (ty << 3) + mi;
        if (gr < n) {
            float4 o0, o1;
            int cb = tx << 3;
            o0.x = fmaxf(acc[mi][0] + bsh[cb + 0], 0.f);
            o0.y = fmaxf(acc[mi][1] + bsh[cb + 1], 0.f);
            o0.z = fmaxf(acc[mi][2] + bsh[cb + 2], 0.f);
            o0.w = fmaxf(acc[mi][3] + bsh[cb + 3], 0.f);
            o1.x = fmaxf(acc[mi][4] + bsh[cb + 4], 0.f);
            o1.y = fmaxf(acc[mi][5] + bsh[cb + 5], 0.f);
            o1.z = fmaxf(acc[mi][6] + bsh[cb + 6], 0.f);
            o1.w = fmaxf(acc[mi][7] + bsh[cb + 7], 0.f);
            *(float4*)(OUT + (size_t)gr * DIM + cb)     = o0;
            *(float4*)(OUT + (size_t)gr * DIM + cb + 4) = o1;
        }
    }
}

// ---------------- launch ----------------
extern "C" void kernel_launch(void* const* d_in, const int* in_sizes, int n_in,
                              void* d_out, int out_size) {
    const float* x_src = (const float*)d_in[0];
    const float* x_dst = (const float*)d_in[1];
    const int*   e_src = (const int*)d_in[2];
    const int*   e_dst = (const int*)d_in[3];
    const float* Wss   = (const float*)d_in[4];   // [2,128,128] ship self
    const float* Wsn   = (const float*)d_in[5];   // ship neigh
    const float* bs    = (const float*)d_in[6];   // [2,128]
    const float* Wrs   = (const float*)d_in[7];   // rev self
    const float* Wrn   = (const float*)d_in[8];   // rev neigh
    const float* br    = (const float*)d_in[9];

    float* out   = (float*)d_out;
    float* out_s = out;                              // reference returns (h_s, h_d)
    float* out_d = out + (size_t)N_NODES * DIM;

    void *p_msg_s, *p_msg_d, *p_h_s, *p_h_d, *p_inv_s, *p_inv_d;
    cudaGetSymbolAddress(&p_msg_s, g_msg_s);
    cudaGetSymbolAddress(&p_msg_d, g_msg_d);
    cudaGetSymbolAddress(&p_h_s,   g_h_s);
    cudaGetSymbolAddress(&p_h_d,   g_h_d);
    cudaGetSymbolAddress(&p_inv_s, g_inv_s);
    cudaGetSymbolAddress(&p_inv_d, g_inv_d);

    cudaFuncSetAttribute(sage_gemm, cudaFuncAttributeMaxDynamicSharedMemorySize,
                         GEMM_SMEM_BYTES);

    cudaStream_t st = 0;
    const size_t featB = (size_t)N_NODES * DIM * sizeof(float);

    // degrees (edge-only, compute once per launch)
    cudaMemsetAsync(p_inv_s, 0, N_NODES * sizeof(float), st);
    cudaMemsetAsync(p_inv_d, 0, N_NODES * sizeof(float), st);
    degree_kernel<<<(E_EDGES + 255) / 256, 256, 0, st>>>(e_src, e_dst);
    invert_kernel<<<(N_NODES + 255) / 256, 256, 0, st>>>();

    const int gemm_grid = (N_NODES + 127) / 128;

    // ---- layer 0 ----
    cudaMemsetAsync(p_msg_s, 0, featB, st);
    cudaMemsetAsync(p_msg_d, 0, featB, st);
    scatter_kernel<<<E_EDGES / 8, 256, 0, st>>>(
        x_src, x_dst, e_src, e_dst, (float*)p_msg_s, (float*)p_msg_d);
    sage_gemm<<<gemm_grid, 256, GEMM_SMEM_BYTES, st>>>(
        x_dst, (const float*)p_msg_d, (const float*)p_inv_d,
        Wss, Wsn, bs, (float*)p_h_d, N_NODES);
    sage_gemm<<<gemm_grid, 256, GEMM_SMEM_BYTES, st>>>(
        x_src, (const float*)p_msg_s, (const float*)p_inv_s,
        Wrs, Wrn, br, (float*)p_h_s, N_NODES);

    // ---- layer 1 (writes final output directly) ----
    const int WOFF = DIM * DIM;   // per-layer weight stride
    cudaMemsetAsync(p_msg_s, 0, featB, st);
    cudaMemsetAsync(p_msg_d, 0, featB, st);
    scatter_kernel<<<E_EDGES / 8, 256, 0, st>>>(
        (const float*)p_h_s, (const float*)p_h_d, e_src, e_dst,
        (float*)p_msg_s, (float*)p_msg_d);
    sage_gemm<<<gemm_grid, 256, GEMM_SMEM_BYTES, st>>>(
        (const float*)p_h_d, (const float*)p_msg_d, (const float*)p_inv_d,
        Wss + WOFF, Wsn + WOFF, bs + DIM, out_d, N_NODES);
    sage_gemm<<<gemm_grid, 256, GEMM_SMEM_BYTES, st>>>(
        (const float*)p_h_s, (const float*)p_msg_s, (const float*)p_inv_s,
        Wrs + WOFF, Wrn + WOFF, br + DIM, out_s, N_NODES);
}

// round 5
// speedup vs baseline: 1.2665x; 1.2665x over previous
#include <cuda_runtime.h>
#include <cuda_bf16.h>
#include <cstdint>

#define N_NODES 100000
#define DIM     128
#define E_EDGES 500000

// ---------------- scratch (no allocations allowed) ----------------
__device__ float g_msg_s[(size_t)N_NODES * DIM];
__device__ float g_msg_d[(size_t)N_NODES * DIM];
__device__ float g_h_s[(size_t)N_NODES * DIM];
__device__ float g_h_d[(size_t)N_NODES * DIM];
__device__ float g_inv_s[N_NODES];
__device__ float g_inv_d[N_NODES];

// ---------------- helpers ----------------
__device__ __forceinline__ uint32_t smem_u32(const void* p) {
    uint32_t a;
    asm("{ .reg .u64 t; cvta.to.shared.u64 t, %1; cvt.u32.u64 %0, t; }"
        : "=r"(a) : "l"(p));
    return a;
}
__device__ __forceinline__ void red_add_v4(float* addr, float4 v) {
    asm volatile("red.global.add.v4.f32 [%0], {%1, %2, %3, %4};"
                 :: "l"(addr), "f"(v.x), "f"(v.y), "f"(v.z), "f"(v.w)
                 : "memory");
}
__device__ __forceinline__ void ldsm4(uint32_t* r, uint32_t addr) {
    asm volatile("ldmatrix.sync.aligned.m8n8.x4.shared.b16 {%0,%1,%2,%3}, [%4];"
                 : "=r"(r[0]), "=r"(r[1]), "=r"(r[2]), "=r"(r[3]) : "r"(addr));
}
__device__ __forceinline__ void ldsm2(uint32_t* r, uint32_t addr) {
    asm volatile("ldmatrix.sync.aligned.m8n8.x2.shared.b16 {%0,%1}, [%2];"
                 : "=r"(r[0]), "=r"(r[1]) : "r"(addr));
}
__device__ __forceinline__ void mma16816(float* c, const uint32_t* a, const uint32_t* b) {
    asm volatile("mma.sync.aligned.m16n8k16.row.col.f32.bf16.bf16.f32 "
                 "{%0,%1,%2,%3}, {%4,%5,%6,%7}, {%8,%9}, {%0,%1,%2,%3};"
                 : "+f"(c[0]), "+f"(c[1]), "+f"(c[2]), "+f"(c[3])
                 : "r"(a[0]), "r"(a[1]), "r"(a[2]), "r"(a[3]),
                   "r"(b[0]), "r"(b[1]));
}
// split 8 fp32 -> 8 bf16 hi + 8 bf16 lo (packed pairs)
__device__ __forceinline__ void split8(float4 a, float4 b, uint4& hi, uint4& lo) {
    float f[8] = {a.x, a.y, a.z, a.w, b.x, b.y, b.z, b.w};
    uint32_t h[8], l[8];
#pragma unroll
    for (int i = 0; i < 8; i++) {
        __nv_bfloat16 hb = __float2bfloat16_rn(f[i]);
        float r = f[i] - __bfloat162float(hb);
        __nv_bfloat16 lb = __float2bfloat16_rn(r);
        h[i] = (uint32_t)*reinterpret_cast<uint16_t*>(&hb);
        l[i] = (uint32_t)*reinterpret_cast<uint16_t*>(&lb);
    }
    hi = make_uint4(h[0] | (h[1] << 16), h[2] | (h[3] << 16),
                    h[4] | (h[5] << 16), h[6] | (h[7] << 16));
    lo = make_uint4(l[0] | (l[1] << 16), l[2] | (l[3] << 16),
                    l[4] | (l[5] << 16), l[6] | (l[7] << 16));
}

// ---------------- SMEM layout (bytes) ----------------
#define A_STR   80        // 32 bf16 (64B) + 16B pad  -> conflict-free ldmatrix
#define B_STR   528       // 256 bf16 (512B) + 16B pad
#define OFF_BIAS 0        // 512B
#define OFF_BH   1024
#define OFF_BL   (OFF_BH + 128 * B_STR)      // 68608
#define OFF_A    (OFF_BL + 128 * B_STR)      // 136192
#define A_HL     (128 * A_STR)               // 10240 (one hi or lo block)
#define A_BUF    (2 * A_HL)                  // 20480 per buffer
#define SMEM_TC  (OFF_A + 2 * A_BUF)         // 177152

// ---------------- degree ----------------
__global__ void degree_kernel(const int* __restrict__ e_src,
                              const int* __restrict__ e_dst) {
    int i = blockIdx.x * blockDim.x + threadIdx.x;
    if (i < E_EDGES) {
        atomicAdd(&g_inv_s[e_src[i]], 1.0f);
        atomicAdd(&g_inv_d[e_dst[i]], 1.0f);
    }
}
__global__ void invert_kernel() {
    int i = blockIdx.x * blockDim.x + threadIdx.x;
    if (i < N_NODES) {
        g_inv_s[i] = 1.0f / fmaxf(g_inv_s[i], 1.0f);
        g_inv_d[i] = 1.0f / fmaxf(g_inv_d[i], 1.0f);
    }
}

// ---------------- fused bidirectional scatter ----------------
__global__ void scatter_kernel(const float* __restrict__ hs,
                               const float* __restrict__ hd,
                               const int* __restrict__ e_src,
                               const int* __restrict__ e_dst,
                               float* __restrict__ msg_s,
                               float* __restrict__ msg_d) {
    int e = blockIdx.x * 8 + (threadIdx.x >> 5);
    int lane = threadIdx.x & 31;
    int src = __ldg(&e_src[e]);
    int dst = __ldg(&e_dst[e]);
    size_t so = (size_t)src * DIM + lane * 4;
    size_t dofs = (size_t)dst * DIM + lane * 4;
    float4 vs = *(const float4*)(hs + so);
    red_add_v4(msg_d + dofs, vs);
    float4 vd = *(const float4*)(hd + dofs);
    red_add_v4(msg_s + so, vd);
}

// ---------------- mma.sync bf16x3 SAGE GEMM ----------------
// OUT = relu( [X | MSG*inv] @ [Wself;Wneigh]^T + b )
// fp32 emulated via bf16 hi/lo split, 3 passes (hh, hl, lh), fp32 accum.
// CTA tile: M=128, N=128, K=256 in 8 chunks of 32. 8 warps, warp tile 64x32.
__global__ __launch_bounds__(256, 1)
void sage_gemm_mma(const float* __restrict__ X, const float* __restrict__ MSG,
                   const float* __restrict__ inv,
                   const float* __restrict__ Wself, const float* __restrict__ Wneigh,
                   const float* __restrict__ bias, float* __restrict__ OUT, int n) {
    extern __shared__ char smem[];
    const uint32_t sb = smem_u32(smem);
    const int tid = threadIdx.x;
    const int lane = tid & 31;
    const int wid = tid >> 5;
    const int warp_m = wid & 1;      // 2 warps over M (64 rows each)
    const int warp_n = wid >> 1;     // 4 warps over N (32 cols each)
    const int m0 = blockIdx.x * 128;

    if (tid < 128) ((float*)(smem + OFF_BIAS))[tid] = bias[tid];

    // ---- B (weights) -> SMEM bf16 hi/lo, rows = n (128), k contiguous (256) ----
    for (int g = tid; g < 4096; g += 256) {
        int nrow = g >> 5;
        int k0 = (g & 31) * 8;
        const float* wsrc = (k0 < 128) ? (Wself + nrow * 128 + k0)
                                       : (Wneigh + nrow * 128 + (k0 - 128));
        float4 f0 = *(const float4*)wsrc;
        float4 f1 = *(const float4*)(wsrc + 4);
        uint4 hi, lo;
        split8(f0, f1, hi, lo);
        *(uint4*)(smem + OFF_BH + nrow * B_STR + k0 * 2) = hi;
        *(uint4*)(smem + OFF_BL + nrow * B_STR + k0 * 2) = lo;
    }

    // ---- A chunk staging: chunk c (32 k): c<4 -> X, c>=4 -> MSG*(1/deg) ----
    const int arow = tid & 127;
    const int akb  = (tid >> 7) * 16;       // 0 or 16 (fp32 elems within chunk)
    const int gr_a = m0 + arow;
    const bool arow_ok = (gr_a < n);
    float4 s0, s1, s2, s3;

    auto ldg_chunk = [&](int c) {
        const bool msg = (c >= 4);
        const float* src = msg ? MSG : X;
        const int kbase = (c & 3) * 32 + akb;
        if (arow_ok) {
            const float4* p = (const float4*)(src + (size_t)gr_a * DIM + kbase);
            s0 = p[0]; s1 = p[1]; s2 = p[2]; s3 = p[3];
            if (msg) {
                float s = __ldg(&inv[gr_a]);
                s0.x *= s; s0.y *= s; s0.z *= s; s0.w *= s;
                s1.x *= s; s1.y *= s; s1.z *= s; s1.w *= s;
                s2.x *= s; s2.y *= s; s2.z *= s; s2.w *= s;
                s3.x *= s; s3.y *= s; s3.z *= s; s3.w *= s;
            }
        } else {
            s0 = make_float4(0.f, 0.f, 0.f, 0.f);
            s1 = s0; s2 = s0; s3 = s0;
        }
    };
    auto sts_chunk = [&](int b) {
        char* ah = smem + OFF_A + b * A_BUF;
        char* al = ah + A_HL;
        uint4 h0, l0, h1, l1;
        split8(s0, s1, h0, l0);
        split8(s2, s3, h1, l1);
        uint32_t off = arow * A_STR + akb * 2;
        *(uint4*)(ah + off)      = h0;
        *(uint4*)(ah + off + 16) = h1;
        *(uint4*)(al + off)      = l0;
        *(uint4*)(al + off + 16) = l1;
    };

    float acc[4][4][4];
#pragma unroll
    for (int mt = 0; mt < 4; mt++)
#pragma unroll
        for (int nt = 0; nt < 4; nt++)
#pragma unroll
            for (int i = 0; i < 4; i++) acc[mt][nt][i] = 0.f;

    ldg_chunk(0);
    sts_chunk(0);
    __syncthreads();

    // ldmatrix lane address components
    const uint32_t a_lrow = (uint32_t)(warp_m * 64 + (lane & 15)) * A_STR
                          + ((lane >> 4) << 3) * 2;            // +8 k for lanes 16-31
    const uint32_t b_lrow = (uint32_t)(warp_n * 32 + (lane & 7)) * B_STR
                          + (lane & 8) * 2;                    // +8 k for lanes 8-15

    for (int c = 0; c < 8; c++) {
        if (c < 7) ldg_chunk(c + 1);

        const uint32_t ah_base = sb + OFF_A + (c & 1) * A_BUF;
        const uint32_t al_base = ah_base + A_HL;
#pragma unroll
        for (int ks = 0; ks < 2; ks++) {
            const uint32_t a_off = a_lrow + (ks * 16) * 2;
            const uint32_t b_off = b_lrow + (c * 32 + ks * 16) * 2;
            uint32_t AH[4][4], AL[4][4], BH[4][2], BL[4][2];
#pragma unroll
            for (int mt = 0; mt < 4; mt++) {
                ldsm4(AH[mt], ah_base + a_off + mt * 16 * A_STR);
                ldsm4(AL[mt], al_base + a_off + mt * 16 * A_STR);
            }
#pragma unroll
            for (int nt = 0; nt < 4; nt++) {
                ldsm2(BH[nt], sb + OFF_BH + b_off + nt * 8 * B_STR);
                ldsm2(BL[nt], sb + OFF_BL + b_off + nt * 8 * B_STR);
            }
#pragma unroll
            for (int mt = 0; mt < 4; mt++)
#pragma unroll
                for (int nt = 0; nt < 4; nt++) {
                    mma16816(acc[mt][nt], AH[mt], BH[nt]);
                    mma16816(acc[mt][nt], AH[mt], BL[nt]);
                    mma16816(acc[mt][nt], AL[mt], BH[nt]);
                }
        }
        __syncthreads();
        if (c < 7) {
            sts_chunk((c + 1) & 1);
            __syncthreads();
        }
    }

    // ---- epilogue: bias + relu ----
    const float* bsh = (const float*)(smem + OFF_BIAS);
#pragma unroll
    for (int mt = 0; mt < 4; mt++) {
        int r0 = m0 + warp_m * 64 + mt * 16 + (lane >> 2);
#pragma unroll
        for (int nt = 0; nt < 4; nt++) {
            int col = warp_n * 32 + nt * 8 + (lane & 3) * 2;
            float b0 = bsh[col], b1 = bsh[col + 1];
            if (r0 < n) {
                float2 v = make_float2(fmaxf(acc[mt][nt][0] + b0, 0.f),
                                       fmaxf(acc[mt][nt][1] + b1, 0.f));
                *(float2*)(OUT + (size_t)r0 * DIM + col) = v;
            }
            if (r0 + 8 < n) {
                float2 v = make_float2(fmaxf(acc[mt][nt][2] + b0, 0.f),
                                       fmaxf(acc[mt][nt][3] + b1, 0.f));
                *(float2*)(OUT + (size_t)(r0 + 8) * DIM + col) = v;
            }
        }
    }
}

// ---------------- launch ----------------
extern "C" void kernel_launch(void* const* d_in, const int* in_sizes, int n_in,
                              void* d_out, int out_size) {
    const float* x_src = (const float*)d_in[0];
    const float* x_dst = (const float*)d_in[1];
    const int*   e_src = (const int*)d_in[2];
    const int*   e_dst = (const int*)d_in[3];
    const float* Wss   = (const float*)d_in[4];
    const float* Wsn   = (const float*)d_in[5];
    const float* bs    = (const float*)d_in[6];
    const float* Wrs   = (const float*)d_in[7];
    const float* Wrn   = (const float*)d_in[8];
    const float* br    = (const float*)d_in[9];

    float* out   = (float*)d_out;
    float* out_s = out;                              // reference returns (h_s, h_d)
    float* out_d = out + (size_t)N_NODES * DIM;

    void *p_msg_s, *p_msg_d, *p_h_s, *p_h_d, *p_inv_s, *p_inv_d;
    cudaGetSymbolAddress(&p_msg_s, g_msg_s);
    cudaGetSymbolAddress(&p_msg_d, g_msg_d);
    cudaGetSymbolAddress(&p_h_s,   g_h_s);
    cudaGetSymbolAddress(&p_h_d,   g_h_d);
    cudaGetSymbolAddress(&p_inv_s, g_inv_s);
    cudaGetSymbolAddress(&p_inv_d, g_inv_d);

    cudaFuncSetAttribute(sage_gemm_mma, cudaFuncAttributeMaxDynamicSharedMemorySize,
                         SMEM_TC);

    cudaStream_t st = 0;
    const size_t featB = (size_t)N_NODES * DIM * sizeof(float);

    cudaMemsetAsync(p_inv_s, 0, N_NODES * sizeof(float), st);
    cudaMemsetAsync(p_inv_d, 0, N_NODES * sizeof(float), st);
    degree_kernel<<<(E_EDGES + 255) / 256, 256, 0, st>>>(e_src, e_dst);
    invert_kernel<<<(N_NODES + 255) / 256, 256, 0, st>>>();

    const int gemm_grid = (N_NODES + 127) / 128;

    // ---- layer 0 ----
    cudaMemsetAsync(p_msg_s, 0, featB, st);
    cudaMemsetAsync(p_msg_d, 0, featB, st);
    scatter_kernel<<<E_EDGES / 8, 256, 0, st>>>(
        x_src, x_dst, e_src, e_dst, (float*)p_msg_s, (float*)p_msg_d);
    sage_gemm_mma<<<gemm_grid, 256, SMEM_TC, st>>>(
        x_dst, (const float*)p_msg_d, (const float*)p_inv_d,
        Wss, Wsn, bs, (float*)p_h_d, N_NODES);
    sage_gemm_mma<<<gemm_grid, 256, SMEM_TC, st>>>(
        x_src, (const float*)p_msg_s, (const float*)p_inv_s,
        Wrs, Wrn, br, (float*)p_h_s, N_NODES);

    // ---- layer 1 ----
    const int WOFF = DIM * DIM;
    cudaMemsetAsync(p_msg_s, 0, featB, st);
    cudaMemsetAsync(p_msg_d, 0, featB, st);
    scatter_kernel<<<E_EDGES / 8, 256, 0, st>>>(
        (const float*)p_h_s, (const float*)p_h_d, e_src, e_dst,
        (float*)p_msg_s, (float*)p_msg_d);
    sage_gemm_mma<<<gemm_grid, 256, SMEM_TC, st>>>(
        (const float*)p_h_d, (const float*)p_msg_d, (const float*)p_inv_d,
        Wss + WOFF, Wsn + WOFF, bs + DIM, out_d, N_NODES);
    sage_gemm_mma<<<gemm_grid, 256, SMEM_TC, st>>>(
        (const float*)p_h_s, (const float*)p_msg_s, (const float*)p_inv_s,
        Wrs + WOFF, Wrn + WOFF, br + DIM, out_s, N_NODES);
}